// round 5
// baseline (speedup 1.0000x reference)
#include <cuda_runtime.h>
#include <cuda_bf16.h>
#include <cstddef>

// Problem shape (fixed by the reference):
//   B=4, T=2048, D=1024, H=16, hd=64
//   x [B,T,D] fp32; W_attn [D,3D]; b_attn [3D]; W_proj [D,D]; b_proj [D]
//   out [B,T,D] fp32

#define BATCH 4
#define SEQ   2048
#define DIM   1024
#define HEADS 16
#define HDIM  64

// Scratch buffers ( __device__ globals: no dynamic allocation allowed )
// q/k/v in [B, H, T, hd] layout; attn output in [B, T, D] layout.
__device__ float g_q[BATCH * HEADS * SEQ * HDIM];
__device__ float g_k[BATCH * HEADS * SEQ * HDIM];
__device__ float g_v[BATCH * HEADS * SEQ * HDIM];
__device__ float g_attn[BATCH * SEQ * DIM];

// ---------------------------------------------------------------------------
// GEMM: C[M,N] = A[M,1024] * B[1024,N] + bias[N]
//   mode 1: A = Ain (= x), epilogue scatters into g_q/g_k/g_v ([B,H,T,hd])
//   mode 0: A = g_attn, epilogue writes Cout[row*N + col] directly
// Tiling: 128x128 block tile, BK=8, 256 threads, 8x8 per-thread microtile.
// ---------------------------------------------------------------------------
#define BM 128
#define BN 128
#define BK 8

__global__ void __launch_bounds__(256) gemm_kernel(
    const float* __restrict__ Ain, const float* __restrict__ Bw,
    const float* __restrict__ bias, float* __restrict__ Cout,
    int Ncols, int mode)
{
    __shared__ float As[BK][BM + 4];   // transposed A tile, padded vs conflicts
    __shared__ float Bs[BK][BN];

    const float* A = (mode == 0) ? g_attn : Ain;

    const int bm = blockIdx.y;
    const int bn = blockIdx.x;
    const int tid = threadIdx.x;
    const int tx = tid & 15;
    const int ty = tid >> 4;

    // A tile load: 128 rows x 8 k, float4 along k, stored transposed.
    const int a_row = tid >> 1;
    const int a_col = (tid & 1) * 4;
    // B tile load: 8 rows x 128 cols, float4 along n.
    const int b_row = tid >> 5;
    const int b_col = (tid & 31) * 4;

    const float* Aptr = A  + (size_t)(bm * BM + a_row) * 1024 + a_col;
    const float* Bptr = Bw + (size_t)b_row * Ncols + bn * BN + b_col;

    float acc[8][8];
    #pragma unroll
    for (int i = 0; i < 8; i++)
        #pragma unroll
        for (int j = 0; j < 8; j++) acc[i][j] = 0.f;

    for (int k0 = 0; k0 < 1024; k0 += BK) {
        float4 av = *(const float4*)(Aptr + k0);
        float4 bv = *(const float4*)(Bptr + (size_t)k0 * Ncols);
        As[a_col + 0][a_row] = av.x;
        As[a_col + 1][a_row] = av.y;
        As[a_col + 2][a_row] = av.z;
        As[a_col + 3][a_row] = av.w;
        *(float4*)&Bs[b_row][b_col] = bv;
        __syncthreads();

        #pragma unroll
        for (int k = 0; k < BK; k++) {
            float4 a0 = *(const float4*)&As[k][ty * 4];
            float4 a1 = *(const float4*)&As[k][64 + ty * 4];
            float4 b0 = *(const float4*)&Bs[k][tx * 4];
            float4 b1 = *(const float4*)&Bs[k][64 + tx * 4];
            float avv[8] = {a0.x, a0.y, a0.z, a0.w, a1.x, a1.y, a1.z, a1.w};
            float bvv[8] = {b0.x, b0.y, b0.z, b0.w, b1.x, b1.y, b1.z, b1.w};
            #pragma unroll
            for (int i = 0; i < 8; i++)
                #pragma unroll
                for (int j = 0; j < 8; j++)
                    acc[i][j] += avv[i] * bvv[j];
        }
        __syncthreads();
    }

    // Epilogue
    #pragma unroll
    for (int i = 0; i < 8; i++) {
        const int lr = (i < 4) ? (ty * 4 + i) : (64 + ty * 4 + (i - 4));
        const int row = bm * BM + lr;
        #pragma unroll
        for (int j = 0; j < 8; j++) {
            const int lc = (j < 4) ? (tx * 4 + j) : (64 + tx * 4 + (j - 4));
            const int col = bn * BN + lc;
            const float val = acc[i][j] + bias[col];
            if (mode == 0) {
                Cout[(size_t)row * Ncols + col] = val;
            } else {
                // scatter qkv[b,t, which*1024 + d] -> g_{q,k,v}[b,h,t,dd]
                const int which = col >> 10;
                const int d  = col & 1023;
                const int h  = d >> 6;
                const int dd = d & 63;
                const int b  = row >> 11;   // row = b*2048 + t
                const int t  = row & 2047;
                float* dst = (which == 0) ? g_q : (which == 1) ? g_k : g_v;
                dst[(((size_t)(b * HEADS + h)) * SEQ + t) * HDIM + dd] = val;
            }
        }
    }
}

// ---------------------------------------------------------------------------
// Flash attention (causal), fp32.
// Grid: (T/64, B*H). Block: 64 threads; thread r owns query row qt*64+r.
// Online softmax in base 2 (scale * log2(e) folded into q once).
// ---------------------------------------------------------------------------
__global__ void __launch_bounds__(64) flash_kernel()
{
    __shared__ float Ks[64][64];
    __shared__ float Vs[64][64];

    const int qt = blockIdx.x;   // query tile
    const int bh = blockIdx.y;   // b*HEADS + h
    const int r  = threadIdx.x;  // 0..63
    const int qrow = qt * 64 + r;

    const float* Qp = g_q + (size_t)bh * SEQ * HDIM;
    const float* Kp = g_k + (size_t)bh * SEQ * HDIM;
    const float* Vp = g_v + (size_t)bh * SEQ * HDIM;

    // fold 1/sqrt(hd) * log2(e) into q
    const float lsc = 1.4426950408889634f * 0.125f;
    float q[64];
    #pragma unroll
    for (int k = 0; k < 64; k += 4) {
        float4 t = *(const float4*)(Qp + (size_t)qrow * HDIM + k);
        q[k]     = t.x * lsc;
        q[k + 1] = t.y * lsc;
        q[k + 2] = t.z * lsc;
        q[k + 3] = t.w * lsc;
    }

    float o[64];
    #pragma unroll
    for (int k = 0; k < 64; k++) o[k] = 0.f;
    float m_run = -1e30f;
    float l = 0.f;

    for (int jt = 0; jt <= qt; jt++) {
        const float* Ksrc = Kp + (size_t)jt * 64 * HDIM;
        const float* Vsrc = Vp + (size_t)jt * 64 * HDIM;
        // cooperative tile load: 64 threads x 16 float4 per buffer
        for (int i = r; i < 1024; i += 64) {
            const int row = i >> 4;
            const int col = (i & 15) << 2;
            *(float4*)&Ks[row][col] = *(const float4*)(Ksrc + row * HDIM + col);
            *(float4*)&Vs[row][col] = *(const float4*)(Vsrc + row * HDIM + col);
        }
        __syncthreads();

        const bool diag = (jt == qt);
        #pragma unroll 1
        for (int js0 = 0; js0 < 64; js0 += 16) {
            if (diag && js0 > r) break;   // fully-masked sub-block for this row

            float s[16];
            #pragma unroll
            for (int jj = 0; jj < 16; jj++) {
                float c0 = 0.f, c1 = 0.f, c2 = 0.f, c3 = 0.f;
                #pragma unroll
                for (int k = 0; k < 64; k += 4) {
                    float4 kv = *(const float4*)&Ks[js0 + jj][k];
                    c0 += q[k]     * kv.x;
                    c1 += q[k + 1] * kv.y;
                    c2 += q[k + 2] * kv.z;
                    c3 += q[k + 3] * kv.w;
                }
                s[jj] = (c0 + c1) + (c2 + c3);
            }
            if (diag) {
                #pragma unroll
                for (int jj = 0; jj < 16; jj++)
                    if (js0 + jj > r) s[jj] = -1e30f;
            }

            float mx = m_run;
            #pragma unroll
            for (int jj = 0; jj < 16; jj++) mx = fmaxf(mx, s[jj]);
            const float factor = exp2f(m_run - mx);
            m_run = mx;
            l *= factor;
            #pragma unroll
            for (int k = 0; k < 64; k++) o[k] *= factor;

            #pragma unroll
            for (int jj = 0; jj < 16; jj++) {
                const float p = exp2f(s[jj] - mx);
                l += p;
                #pragma unroll
                for (int k = 0; k < 64; k += 4) {
                    float4 vv = *(const float4*)&Vs[js0 + jj][k];
                    o[k]     += p * vv.x;
                    o[k + 1] += p * vv.y;
                    o[k + 2] += p * vv.z;
                    o[k + 3] += p * vv.w;
                }
            }
        }
        __syncthreads();
    }

    const float inv = 1.f / l;
    const int b = bh >> 4;
    const int h = bh & 15;
    float* dst = g_attn + ((size_t)b * SEQ + qrow) * DIM + h * HDIM;
    #pragma unroll
    for (int k = 0; k < 64; k += 4) {
        float4 t;
        t.x = o[k] * inv;
        t.y = o[k + 1] * inv;
        t.z = o[k + 2] * inv;
        t.w = o[k + 3] * inv;
        *(float4*)(dst + k) = t;
    }
}

// ---------------------------------------------------------------------------
// Launch
// ---------------------------------------------------------------------------
extern "C" void kernel_launch(void* const* d_in, const int* in_sizes, int n_in,
                              void* d_out, int out_size)
{
    const float* x      = (const float*)d_in[0];  // [4,2048,1024]
    const float* W_attn = (const float*)d_in[1];  // [1024,3072]
    const float* b_attn = (const float*)d_in[2];  // [3072]
    const float* W_proj = (const float*)d_in[3];  // [1024,1024]
    const float* b_proj = (const float*)d_in[4];  // [1024]
    float* out = (float*)d_out;                   // [4,2048,1024]

    (void)in_sizes; (void)n_in; (void)out_size;

    // 1) QKV GEMM: [8192,1024] x [1024,3072] + bias, scatter to g_q/g_k/g_v
    gemm_kernel<<<dim3(3072 / BN, 8192 / BM), 256>>>(
        x, W_attn, b_attn, nullptr, 3072, /*mode=*/1);

    // 2) Causal flash attention -> g_attn [B,T,D]
    flash_kernel<<<dim3(SEQ / 64, BATCH * HEADS), 64>>>();

    // 3) Output projection: g_attn [8192,1024] x [1024,1024] + bias -> out
    gemm_kernel<<<dim3(1024 / BN, 8192 / BM), 256>>>(
        nullptr, W_proj, b_proj, out, 1024, /*mode=*/0);
}

// round 11
// speedup vs baseline: 1.2925x; 1.2925x over previous
#include <cuda_runtime.h>
#include <cuda_bf16.h>
#include <cstdint>
#include <cstddef>

// Problem shape: B=4, T=2048, D=1024, H=16, hd=64
#define BATCH 4
#define SEQ   2048
#define DIM   1024
#define HEADS 16
#define HDIM  64

// ---------------------------------------------------------------------------
// Device-global scratch (no dynamic allocation allowed)
// ---------------------------------------------------------------------------
__device__ __align__(16) float g_q[BATCH * HEADS * SEQ * HDIM];
__device__ __align__(16) float g_k[BATCH * HEADS * SEQ * HDIM];
__device__ __align__(16) float g_v[BATCH * HEADS * SEQ * HDIM];
__device__ __align__(16) float g_attn[BATCH * SEQ * DIM];

// split-bf16 operands: weights transposed to [N][K], activations [M][K]
__device__ __align__(16) __nv_bfloat16 g_wat_hi[3072 * 1024];
__device__ __align__(16) __nv_bfloat16 g_wat_lo[3072 * 1024];
__device__ __align__(16) __nv_bfloat16 g_wpt_hi[1024 * 1024];
__device__ __align__(16) __nv_bfloat16 g_wpt_lo[1024 * 1024];
__device__ __align__(16) __nv_bfloat16 g_a_hi[8192 * 1024];
__device__ __align__(16) __nv_bfloat16 g_a_lo[8192 * 1024];

// ---------------------------------------------------------------------------
// Portable PTX helpers (base-target features only: sm_80 mma.sync / ldmatrix /
// cp.async — NO tcgen05/TMA, which ptxas rejects under compute_103)
// ---------------------------------------------------------------------------
__device__ __forceinline__ uint32_t smem_u32(const void* p) {
    uint32_t a;
    asm("{ .reg .u64 t; cvta.to.shared.u64 t, %1; cvt.u32.u64 %0, t; }"
        : "=r"(a) : "l"(p));
    return a;
}

#define CP16(smem, gptr) \
    asm volatile("cp.async.cg.shared.global [%0], [%1], 16;" \
                 :: "r"(smem), "l"(gptr))
#define CP_COMMIT() asm volatile("cp.async.commit_group;" ::: "memory")
#define CP_WAIT1()  asm volatile("cp.async.wait_group 1;" ::: "memory")
#define CP_WAIT0()  asm volatile("cp.async.wait_group 0;" ::: "memory")

#define LDM_X4(r, addr) \
    asm volatile("ldmatrix.sync.aligned.m8n8.x4.shared.b16 {%0,%1,%2,%3}, [%4];" \
                 : "=r"((r)[0]), "=r"((r)[1]), "=r"((r)[2]), "=r"((r)[3]) \
                 : "r"(addr))

__device__ __forceinline__ void mma16816(float* d, const uint32_t* a,
                                         const uint32_t* b) {
    asm volatile(
        "mma.sync.aligned.m16n8k16.row.col.f32.bf16.bf16.f32 "
        "{%0,%1,%2,%3}, {%4,%5,%6,%7}, {%8,%9}, {%0,%1,%2,%3};"
        : "+f"(d[0]), "+f"(d[1]), "+f"(d[2]), "+f"(d[3])
        : "r"(a[0]), "r"(a[1]), "r"(a[2]), "r"(a[3]), "r"(b[0]), "r"(b[1]));
}

// ---------------------------------------------------------------------------
// Weight transpose + split: W[K=1024][N] -> Wt_hi/lo[N][1024] bf16
// which: 1 = W_attn -> g_wat, 0 = W_proj -> g_wpt
// ---------------------------------------------------------------------------
__global__ void __launch_bounds__(256) wsplit_kernel(const float* __restrict__ W,
                                                     int N, int which) {
    __shared__ float tile[32][33];
    __nv_bfloat16* hi = which ? g_wat_hi : g_wpt_hi;
    __nv_bfloat16* lo = which ? g_wat_lo : g_wpt_lo;
    const int n0 = blockIdx.x * 32, k0 = blockIdx.y * 32;
    const int tx = threadIdx.x, ty = threadIdx.y;  // 32 x 8
    for (int i = ty; i < 32; i += 8)
        tile[i][tx] = W[(size_t)(k0 + i) * N + n0 + tx];
    __syncthreads();
    for (int j = ty; j < 32; j += 8) {
        const int n = n0 + j, k = k0 + tx;
        const float v = tile[tx][j];
        const __nv_bfloat16 h = __float2bfloat16(v);
        const float r = v - __bfloat162float(h);
        hi[(size_t)n * 1024 + k] = h;
        lo[(size_t)n * 1024 + k] = __float2bfloat16(r);
    }
}

// ---------------------------------------------------------------------------
// Activation split: src[M][1024] fp32 -> g_a_hi/lo bf16 (src==null => g_attn)
// ---------------------------------------------------------------------------
__global__ void __launch_bounds__(256) asplit_kernel(const float* __restrict__ src) {
    const int i = blockIdx.x * 256 + threadIdx.x;  // indexes float4
    const float4 v = ((const float4*)(src ? src : g_attn))[i];
    __nv_bfloat16 h0 = __float2bfloat16(v.x), h1 = __float2bfloat16(v.y);
    __nv_bfloat16 h2 = __float2bfloat16(v.z), h3 = __float2bfloat16(v.w);
    __nv_bfloat16 l0 = __float2bfloat16(v.x - __bfloat162float(h0));
    __nv_bfloat16 l1 = __float2bfloat16(v.y - __bfloat162float(h1));
    __nv_bfloat16 l2 = __float2bfloat16(v.z - __bfloat162float(h2));
    __nv_bfloat16 l3 = __float2bfloat16(v.w - __bfloat162float(h3));
    uint2 ph, pl;
    ph.x = (uint32_t)reinterpret_cast<unsigned short&>(h0) |
           ((uint32_t)reinterpret_cast<unsigned short&>(h1) << 16);
    ph.y = (uint32_t)reinterpret_cast<unsigned short&>(h2) |
           ((uint32_t)reinterpret_cast<unsigned short&>(h3) << 16);
    pl.x = (uint32_t)reinterpret_cast<unsigned short&>(l0) |
           ((uint32_t)reinterpret_cast<unsigned short&>(l1) << 16);
    pl.y = (uint32_t)reinterpret_cast<unsigned short&>(l2) |
           ((uint32_t)reinterpret_cast<unsigned short&>(l3) << 16);
    ((uint2*)g_a_hi)[i] = ph;
    ((uint2*)g_a_lo)[i] = pl;
}

// ---------------------------------------------------------------------------
// mma.sync split-bf16 GEMM: C[M,N] = A[M,1024] * Wt[N,1024]^T + bias
//   CTA tile 128x128, 8 warps (warp tile 32x64), K-stage 32, cp.async 2-stage.
//   mode 1: W = g_wat (QKV), epilogue scatters to g_q/g_k/g_v
//   mode 0: W = g_wpt (proj), epilogue writes Cout
// ---------------------------------------------------------------------------
#define KT     32
#define ROWB   80                  // padded row: 40 bf16 = 80 B (conflict-free ldmatrix)
#define TILE_B (128 * ROWB)        // 10240 B per operand tile
#define STAGE  (4 * TILE_B)        // Ah, Al, Bh, Bl
#define DYN_SMEM (2 * STAGE)       // 81920 B

__global__ void __launch_bounds__(256) mma_gemm_kernel(const float* __restrict__ bias,
                                                       float* __restrict__ Cout,
                                                       int Ncols, int mode) {
    extern __shared__ char sm[];
    const int tid = threadIdx.x, lane = tid & 31, wid = tid >> 5;
    const int wm = wid & 3, wn = wid >> 2;       // warp grid 4 (M) x 2 (N)
    const int n0 = blockIdx.x * 128, m0 = blockIdx.y * 128;
    const uint32_t base = smem_u32(sm);

    const __nv_bfloat16* srcs[4] = {
        g_a_hi + (size_t)m0 * 1024,
        g_a_lo + (size_t)m0 * 1024,
        (mode ? g_wat_hi : g_wpt_hi) + (size_t)n0 * 1024,
        (mode ? g_wat_lo : g_wpt_lo) + (size_t)n0 * 1024};

    float acc[2][8][4];
    #pragma unroll
    for (int i = 0; i < 2; i++)
        #pragma unroll
        for (int j = 0; j < 8; j++)
            #pragma unroll
            for (int c = 0; c < 4; c++) acc[i][j][c] = 0.f;

    // ldmatrix per-lane address components
    const int arow = lane & 15, aseg = lane >> 4;
    const int nrow = (lane & 7) + ((lane >> 4) << 3);
    const int kseg = (lane >> 3) & 1;

    // stage issue: 4 tiles x 512 16B-chunks, 8 chunks/thread
    #define ISSUE_STAGE(s) do {                                                   \
        const int _buf = (s) & 1;                                                 \
        const int _k0 = (s) * KT;                                                 \
        const uint32_t _sb = base + _buf * STAGE;                                 \
        _Pragma("unroll")                                                         \
        for (int _c = 0; _c < 8; _c++) {                                          \
            const int _g = tid + _c * 256;                                        \
            const int _tile = _g >> 9, _t = _g & 511;                             \
            const int _row = _t >> 2, _seg = _t & 3;                              \
            CP16(_sb + _tile * TILE_B + _row * ROWB + _seg * 16,                  \
                 srcs[_tile] + (size_t)_row * 1024 + _k0 + _seg * 8);             \
        }                                                                         \
        CP_COMMIT();                                                              \
    } while (0)

    ISSUE_STAGE(0);
    for (int s = 0; s < 32; s++) {
        if (s + 1 < 32) { ISSUE_STAGE(s + 1); CP_WAIT1(); }
        else            { CP_WAIT0(); }
        __syncthreads();

        const uint32_t sb  = base + (s & 1) * STAGE;
        const uint32_t sAh = sb, sAl = sb + TILE_B;
        const uint32_t sBh = sb + 2 * TILE_B, sBl = sb + 3 * TILE_B;

        #pragma unroll
        for (int ks = 0; ks < 2; ks++) {
            const int kk = ks * 16;
            uint32_t Ah[2][4], Al[2][4];
            #pragma unroll
            for (int ms = 0; ms < 2; ms++) {
                const uint32_t aoff =
                    (uint32_t)((wm * 32 + ms * 16 + arow) * ROWB + (kk + aseg * 8) * 2);
                LDM_X4(Ah[ms], sAh + aoff);
                LDM_X4(Al[ms], sAl + aoff);
            }
            uint32_t Bh[8][2], Bl[8][2];
            #pragma unroll
            for (int np = 0; np < 4; np++) {
                const uint32_t boff =
                    (uint32_t)((wn * 64 + np * 16 + nrow) * ROWB + (kk + kseg * 8) * 2);
                uint32_t t0[4], t1[4];
                LDM_X4(t0, sBh + boff);
                Bh[np * 2][0] = t0[0]; Bh[np * 2][1] = t0[1];
                Bh[np * 2 + 1][0] = t0[2]; Bh[np * 2 + 1][1] = t0[3];
                LDM_X4(t1, sBl + boff);
                Bl[np * 2][0] = t1[0]; Bl[np * 2][1] = t1[1];
                Bl[np * 2 + 1][0] = t1[2]; Bl[np * 2 + 1][1] = t1[3];
            }
            #pragma unroll
            for (int ms = 0; ms < 2; ms++)
                #pragma unroll
                for (int ns = 0; ns < 8; ns++) {
                    mma16816(acc[ms][ns], Ah[ms], Bh[ns]);
                    mma16816(acc[ms][ns], Ah[ms], Bl[ns]);
                    mma16816(acc[ms][ns], Al[ms], Bh[ns]);
                }
        }
        __syncthreads();
    }

    // Epilogue: C frag -> (row, col) pairs, add bias, write / scatter
    #pragma unroll
    for (int ms = 0; ms < 2; ms++) {
        const int r0 = m0 + wm * 32 + ms * 16 + (lane >> 2);
        #pragma unroll
        for (int ns = 0; ns < 8; ns++) {
            const int col = n0 + wn * 64 + ns * 8 + (lane & 3) * 2;
            const float b0 = bias[col], b1 = bias[col + 1];
            float2 v0 = make_float2(acc[ms][ns][0] + b0, acc[ms][ns][1] + b1);
            float2 v1 = make_float2(acc[ms][ns][2] + b0, acc[ms][ns][3] + b1);
            if (mode == 0) {
                *(float2*)(Cout + (size_t)r0 * Ncols + col) = v0;
                *(float2*)(Cout + (size_t)(r0 + 8) * Ncols + col) = v1;
            } else {
                const int which = col >> 10;
                const int d  = col & 1023;
                const int h  = d >> 6;
                const int dd = d & 63;
                float* dst = (which == 0) ? g_q : (which == 1) ? g_k : g_v;
                {
                    const int b = r0 >> 11, t = r0 & 2047;
                    *(float2*)(dst + (((size_t)(b * HEADS + h)) * SEQ + t) * HDIM + dd) = v0;
                }
                {
                    const int r1 = r0 + 8;
                    const int b = r1 >> 11, t = r1 & 2047;
                    *(float2*)(dst + (((size_t)(b * HEADS + h)) * SEQ + t) * HDIM + dd) = v1;
                }
            }
        }
    }
}

// ---------------------------------------------------------------------------
// Flash attention (causal), fp32 — unchanged from the measured baseline.
// ---------------------------------------------------------------------------
__global__ void __launch_bounds__(64) flash_kernel() {
    __shared__ float Ks[64][64];
    __shared__ float Vs[64][64];

    const int qt = blockIdx.x;
    const int bh = blockIdx.y;
    const int r  = threadIdx.x;
    const int qrow = qt * 64 + r;

    const float* Qp = g_q + (size_t)bh * SEQ * HDIM;
    const float* Kp = g_k + (size_t)bh * SEQ * HDIM;
    const float* Vp = g_v + (size_t)bh * SEQ * HDIM;

    const float lsc = 1.4426950408889634f * 0.125f;
    float q[64];
    #pragma unroll
    for (int k = 0; k < 64; k += 4) {
        float4 t = *(const float4*)(Qp + (size_t)qrow * HDIM + k);
        q[k] = t.x * lsc; q[k + 1] = t.y * lsc; q[k + 2] = t.z * lsc; q[k + 3] = t.w * lsc;
    }

    float o[64];
    #pragma unroll
    for (int k = 0; k < 64; k++) o[k] = 0.f;
    float m_run = -1e30f;
    float l = 0.f;

    for (int jt = 0; jt <= qt; jt++) {
        const float* Ksrc = Kp + (size_t)jt * 64 * HDIM;
        const float* Vsrc = Vp + (size_t)jt * 64 * HDIM;
        for (int i = r; i < 1024; i += 64) {
            const int row = i >> 4;
            const int col = (i & 15) << 2;
            *(float4*)&Ks[row][col] = *(const float4*)(Ksrc + row * HDIM + col);
            *(float4*)&Vs[row][col] = *(const float4*)(Vsrc + row * HDIM + col);
        }
        __syncthreads();

        const bool diag = (jt == qt);
        #pragma unroll 1
        for (int js0 = 0; js0 < 64; js0 += 16) {
            if (diag && js0 > r) break;

            float s[16];
            #pragma unroll
            for (int jj = 0; jj < 16; jj++) {
                float c0 = 0.f, c1 = 0.f, c2 = 0.f, c3 = 0.f;
                #pragma unroll
                for (int k = 0; k < 64; k += 4) {
                    float4 kv = *(const float4*)&Ks[js0 + jj][k];
                    c0 += q[k]     * kv.x;
                    c1 += q[k + 1] * kv.y;
                    c2 += q[k + 2] * kv.z;
                    c3 += q[k + 3] * kv.w;
                }
                s[jj] = (c0 + c1) + (c2 + c3);
            }
            if (diag) {
                #pragma unroll
                for (int jj = 0; jj < 16; jj++)
                    if (js0 + jj > r) s[jj] = -1e30f;
            }

            float mx = m_run;
            #pragma unroll
            for (int jj = 0; jj < 16; jj++) mx = fmaxf(mx, s[jj]);
            const float factor = exp2f(m_run - mx);
            m_run = mx;
            l *= factor;
            #pragma unroll
            for (int k = 0; k < 64; k++) o[k] *= factor;

            #pragma unroll
            for (int jj = 0; jj < 16; jj++) {
                const float p = exp2f(s[jj] - mx);
                l += p;
                #pragma unroll
                for (int k = 0; k < 64; k += 4) {
                    float4 vv = *(const float4*)&Vs[js0 + jj][k];
                    o[k]     += p * vv.x;
                    o[k + 1] += p * vv.y;
                    o[k + 2] += p * vv.z;
                    o[k + 3] += p * vv.w;
                }
            }
        }
        __syncthreads();
    }

    const float inv = 1.f / l;
    const int b = bh >> 4;
    const int h = bh & 15;
    float* dst = g_attn + ((size_t)b * SEQ + qrow) * DIM + h * HDIM;
    #pragma unroll
    for (int k = 0; k < 64; k += 4) {
        float4 t;
        t.x = o[k] * inv; t.y = o[k + 1] * inv; t.z = o[k + 2] * inv; t.w = o[k + 3] * inv;
        *(float4*)(dst + k) = t;
    }
}

// ---------------------------------------------------------------------------
// Launch
// ---------------------------------------------------------------------------
extern "C" void kernel_launch(void* const* d_in, const int* in_sizes, int n_in,
                              void* d_out, int out_size) {
    const float* x      = (const float*)d_in[0];
    const float* W_attn = (const float*)d_in[1];
    const float* b_attn = (const float*)d_in[2];
    const float* W_proj = (const float*)d_in[3];
    const float* b_proj = (const float*)d_in[4];
    float* out = (float*)d_out;
    (void)in_sizes; (void)n_in; (void)out_size;

    cudaFuncSetAttribute(mma_gemm_kernel,
                         cudaFuncAttributeMaxDynamicSharedMemorySize, DYN_SMEM);

    // weight transpose+split
    wsplit_kernel<<<dim3(3072 / 32, 1024 / 32), dim3(32, 8)>>>(W_attn, 3072, 1);
    wsplit_kernel<<<dim3(1024 / 32, 1024 / 32), dim3(32, 8)>>>(W_proj, 1024, 0);

    // x -> bf16 hi/lo
    asplit_kernel<<<8192, 256>>>(x);

    // QKV GEMM (mma.sync split-bf16), scatter to g_q/g_k/g_v
    mma_gemm_kernel<<<dim3(3072 / 128, 8192 / 128), 256, DYN_SMEM>>>(
        b_attn, nullptr, 3072, /*mode=*/1);

    // causal flash attention -> g_attn
    flash_kernel<<<dim3(SEQ / 64, BATCH * HEADS), 64>>>();

    // g_attn -> bf16 hi/lo
    asplit_kernel<<<8192, 256>>>(nullptr);

    // output projection
    mma_gemm_kernel<<<dim3(1024 / 128, 8192 / 128), 256, DYN_SMEM>>>(
        b_proj, out, 1024, /*mode=*/0);
}

// round 12
// speedup vs baseline: 3.1407x; 2.4299x over previous
#include <cuda_runtime.h>
#include <cuda_bf16.h>
#include <cstdint>
#include <cstddef>

// Problem shape: B=4, T=2048, D=1024, H=16, hd=64
#define BATCH 4
#define SEQ   2048
#define DIM   1024
#define HEADS 16
#define HDIM  64

// ---------------------------------------------------------------------------
// Device-global scratch (no dynamic allocation allowed)
// q/k/v stored as split bf16 hi/lo, [b*H+h][t][hd]; Q pre-scaled by log2e/8.
// ---------------------------------------------------------------------------
__device__ __align__(16) __nv_bfloat16 g_qh[BATCH * HEADS * SEQ * HDIM];
__device__ __align__(16) __nv_bfloat16 g_ql[BATCH * HEADS * SEQ * HDIM];
__device__ __align__(16) __nv_bfloat16 g_kh[BATCH * HEADS * SEQ * HDIM];
__device__ __align__(16) __nv_bfloat16 g_kl[BATCH * HEADS * SEQ * HDIM];
__device__ __align__(16) __nv_bfloat16 g_vh[BATCH * HEADS * SEQ * HDIM];
__device__ __align__(16) __nv_bfloat16 g_vl[BATCH * HEADS * SEQ * HDIM];

// split-bf16 GEMM operands: weights transposed [N][K]; activations [M][K]
__device__ __align__(16) __nv_bfloat16 g_wat_hi[3072 * 1024];
__device__ __align__(16) __nv_bfloat16 g_wat_lo[3072 * 1024];
__device__ __align__(16) __nv_bfloat16 g_wpt_hi[1024 * 1024];
__device__ __align__(16) __nv_bfloat16 g_wpt_lo[1024 * 1024];
__device__ __align__(16) __nv_bfloat16 g_a_hi[8192 * 1024];
__device__ __align__(16) __nv_bfloat16 g_a_lo[8192 * 1024];

// log2(e) / sqrt(hd)
#define LSC 0.18033688011112042f

// ---------------------------------------------------------------------------
// Portable PTX helpers (sm_80 feature set only; tcgen05/TMA rejected by
// the harness's compute_103 virtual-arch build)
// ---------------------------------------------------------------------------
__device__ __forceinline__ uint32_t smem_u32(const void* p) {
    uint32_t a;
    asm("{ .reg .u64 t; cvta.to.shared.u64 t, %1; cvt.u32.u64 %0, t; }"
        : "=r"(a) : "l"(p));
    return a;
}

#define CP16(smem, gptr) \
    asm volatile("cp.async.cg.shared.global [%0], [%1], 16;" \
                 :: "r"(smem), "l"(gptr))
#define CP_COMMIT() asm volatile("cp.async.commit_group;" ::: "memory")
#define CP_WAIT1()  asm volatile("cp.async.wait_group 1;" ::: "memory")
#define CP_WAIT0()  asm volatile("cp.async.wait_group 0;" ::: "memory")

#define LDM_X4(r, addr) \
    asm volatile("ldmatrix.sync.aligned.m8n8.x4.shared.b16 {%0,%1,%2,%3}, [%4];" \
                 : "=r"((r)[0]), "=r"((r)[1]), "=r"((r)[2]), "=r"((r)[3]) \
                 : "r"(addr))

#define LDM_X4_T(r, addr) \
    asm volatile("ldmatrix.sync.aligned.m8n8.x4.trans.shared.b16 {%0,%1,%2,%3}, [%4];" \
                 : "=r"((r)[0]), "=r"((r)[1]), "=r"((r)[2]), "=r"((r)[3]) \
                 : "r"(addr))

__device__ __forceinline__ void mma16816(float* d, const uint32_t* a,
                                         const uint32_t* b) {
    asm volatile(
        "mma.sync.aligned.m16n8k16.row.col.f32.bf16.bf16.f32 "
        "{%0,%1,%2,%3}, {%4,%5,%6,%7}, {%8,%9}, {%0,%1,%2,%3};"
        : "+f"(d[0]), "+f"(d[1]), "+f"(d[2]), "+f"(d[3])
        : "r"(a[0]), "r"(a[1]), "r"(a[2]), "r"(a[3]), "r"(b[0]), "r"(b[1]));
}

__device__ __forceinline__ float ex2(float x) {
    float r;
    asm("ex2.approx.f32 %0, %1;" : "=f"(r) : "f"(x));
    return r;
}

// split (a,b) into bf16 hi/lo packed pairs (low half = a)
__device__ __forceinline__ void splitpack(float a, float b,
                                          uint32_t& hi, uint32_t& lo) {
    __nv_bfloat16 ha = __float2bfloat16(a), hb = __float2bfloat16(b);
    float la = a - __bfloat162float(ha), lb = b - __bfloat162float(hb);
    __nv_bfloat162 hv; hv.x = ha; hv.y = hb;
    __nv_bfloat162 lv; lv.x = __float2bfloat16(la); lv.y = __float2bfloat16(lb);
    hi = *reinterpret_cast<uint32_t*>(&hv);
    lo = *reinterpret_cast<uint32_t*>(&lv);
}

__device__ __forceinline__ void split_store(__nv_bfloat16* dh, __nv_bfloat16* dl,
                                            size_t idx, float a, float b) {
    __nv_bfloat16 ha = __float2bfloat16(a), hb = __float2bfloat16(b);
    float la = a - __bfloat162float(ha), lb = b - __bfloat162float(hb);
    __nv_bfloat162 hv; hv.x = ha; hv.y = hb;
    __nv_bfloat162 lv; lv.x = __float2bfloat16(la); lv.y = __float2bfloat16(lb);
    *reinterpret_cast<__nv_bfloat162*>(dh + idx) = hv;
    *reinterpret_cast<__nv_bfloat162*>(dl + idx) = lv;
}

// ---------------------------------------------------------------------------
// Weight transpose + split: W[K=1024][N] -> Wt_hi/lo[N][1024] bf16
// ---------------------------------------------------------------------------
__global__ void __launch_bounds__(256) wsplit_kernel(const float* __restrict__ W,
                                                     int N, int which) {
    __shared__ float tile[32][33];
    __nv_bfloat16* hi = which ? g_wat_hi : g_wpt_hi;
    __nv_bfloat16* lo = which ? g_wat_lo : g_wpt_lo;
    const int n0 = blockIdx.x * 32, k0 = blockIdx.y * 32;
    const int tx = threadIdx.x, ty = threadIdx.y;
    for (int i = ty; i < 32; i += 8)
        tile[i][tx] = W[(size_t)(k0 + i) * N + n0 + tx];
    __syncthreads();
    for (int j = ty; j < 32; j += 8) {
        const int n = n0 + j, k = k0 + tx;
        const float v = tile[tx][j];
        const __nv_bfloat16 h = __float2bfloat16(v);
        hi[(size_t)n * 1024 + k] = h;
        lo[(size_t)n * 1024 + k] = __float2bfloat16(v - __bfloat162float(h));
    }
}

// ---------------------------------------------------------------------------
// Activation split: x[M][1024] fp32 -> g_a_hi/lo bf16
// ---------------------------------------------------------------------------
__global__ void __launch_bounds__(256) asplit_kernel(const float* __restrict__ src) {
    const int i = blockIdx.x * 256 + threadIdx.x;
    const float4 v = ((const float4*)src)[i];
    __nv_bfloat16 h0 = __float2bfloat16(v.x), h1 = __float2bfloat16(v.y);
    __nv_bfloat16 h2 = __float2bfloat16(v.z), h3 = __float2bfloat16(v.w);
    __nv_bfloat16 l0 = __float2bfloat16(v.x - __bfloat162float(h0));
    __nv_bfloat16 l1 = __float2bfloat16(v.y - __bfloat162float(h1));
    __nv_bfloat16 l2 = __float2bfloat16(v.z - __bfloat162float(h2));
    __nv_bfloat16 l3 = __float2bfloat16(v.w - __bfloat162float(h3));
    uint2 ph, pl;
    ph.x = (uint32_t)reinterpret_cast<unsigned short&>(h0) |
           ((uint32_t)reinterpret_cast<unsigned short&>(h1) << 16);
    ph.y = (uint32_t)reinterpret_cast<unsigned short&>(h2) |
           ((uint32_t)reinterpret_cast<unsigned short&>(h3) << 16);
    pl.x = (uint32_t)reinterpret_cast<unsigned short&>(l0) |
           ((uint32_t)reinterpret_cast<unsigned short&>(l1) << 16);
    pl.y = (uint32_t)reinterpret_cast<unsigned short&>(l2) |
           ((uint32_t)reinterpret_cast<unsigned short&>(l3) << 16);
    ((uint2*)g_a_hi)[i] = ph;
    ((uint2*)g_a_lo)[i] = pl;
}

// ---------------------------------------------------------------------------
// mma.sync split-bf16 GEMM (validated R11). mode 1: QKV, epilogue scatters
// split-bf16 q/k/v (Q scaled by LSC). mode 0: proj, writes fp32 Cout.
// ---------------------------------------------------------------------------
#define KT     32
#define ROWB   80
#define TILE_B (128 * ROWB)
#define STAGE  (4 * TILE_B)
#define DYN_SMEM (2 * STAGE)

__global__ void __launch_bounds__(256) mma_gemm_kernel(const float* __restrict__ bias,
                                                       float* __restrict__ Cout,
                                                       int Ncols, int mode) {
    extern __shared__ char sm[];
    const int tid = threadIdx.x, lane = tid & 31, wid = tid >> 5;
    const int wm = wid & 3, wn = wid >> 2;
    const int n0 = blockIdx.x * 128, m0 = blockIdx.y * 128;
    const uint32_t base = smem_u32(sm);

    const __nv_bfloat16* srcs[4] = {
        g_a_hi + (size_t)m0 * 1024,
        g_a_lo + (size_t)m0 * 1024,
        (mode ? g_wat_hi : g_wpt_hi) + (size_t)n0 * 1024,
        (mode ? g_wat_lo : g_wpt_lo) + (size_t)n0 * 1024};

    float acc[2][8][4];
    #pragma unroll
    for (int i = 0; i < 2; i++)
        #pragma unroll
        for (int j = 0; j < 8; j++)
            #pragma unroll
            for (int c = 0; c < 4; c++) acc[i][j][c] = 0.f;

    const int arow = lane & 15, aseg = lane >> 4;
    const int nrow = (lane & 7) + ((lane >> 4) << 3);
    const int kseg = (lane >> 3) & 1;

    #define ISSUE_STAGE(s) do {                                                   \
        const int _buf = (s) & 1;                                                 \
        const int _k0 = (s) * KT;                                                 \
        const uint32_t _sb = base + _buf * STAGE;                                 \
        _Pragma("unroll")                                                         \
        for (int _c = 0; _c < 8; _c++) {                                          \
            const int _g = tid + _c * 256;                                        \
            const int _tile = _g >> 9, _t = _g & 511;                             \
            const int _row = _t >> 2, _seg = _t & 3;                              \
            CP16(_sb + _tile * TILE_B + _row * ROWB + _seg * 16,                  \
                 srcs[_tile] + (size_t)_row * 1024 + _k0 + _seg * 8);             \
        }                                                                         \
        CP_COMMIT();                                                              \
    } while (0)

    ISSUE_STAGE(0);
    for (int s = 0; s < 32; s++) {
        if (s + 1 < 32) { ISSUE_STAGE(s + 1); CP_WAIT1(); }
        else            { CP_WAIT0(); }
        __syncthreads();

        const uint32_t sb  = base + (s & 1) * STAGE;
        const uint32_t sAh = sb, sAl = sb + TILE_B;
        const uint32_t sBh = sb + 2 * TILE_B, sBl = sb + 3 * TILE_B;

        #pragma unroll
        for (int ks = 0; ks < 2; ks++) {
            const int kk = ks * 16;
            uint32_t Ah[2][4], Al[2][4];
            #pragma unroll
            for (int ms = 0; ms < 2; ms++) {
                const uint32_t aoff =
                    (uint32_t)((wm * 32 + ms * 16 + arow) * ROWB + (kk + aseg * 8) * 2);
                LDM_X4(Ah[ms], sAh + aoff);
                LDM_X4(Al[ms], sAl + aoff);
            }
            uint32_t Bh[8][2], Bl[8][2];
            #pragma unroll
            for (int np = 0; np < 4; np++) {
                const uint32_t boff =
                    (uint32_t)((wn * 64 + np * 16 + nrow) * ROWB + (kk + kseg * 8) * 2);
                uint32_t t0[4], t1[4];
                LDM_X4(t0, sBh + boff);
                Bh[np * 2][0] = t0[0]; Bh[np * 2][1] = t0[1];
                Bh[np * 2 + 1][0] = t0[2]; Bh[np * 2 + 1][1] = t0[3];
                LDM_X4(t1, sBl + boff);
                Bl[np * 2][0] = t1[0]; Bl[np * 2][1] = t1[1];
                Bl[np * 2 + 1][0] = t1[2]; Bl[np * 2 + 1][1] = t1[3];
            }
            #pragma unroll
            for (int ms = 0; ms < 2; ms++)
                #pragma unroll
                for (int ns = 0; ns < 8; ns++) {
                    mma16816(acc[ms][ns], Ah[ms], Bh[ns]);
                    mma16816(acc[ms][ns], Ah[ms], Bl[ns]);
                    mma16816(acc[ms][ns], Al[ms], Bh[ns]);
                }
        }
        __syncthreads();
    }

    #pragma unroll
    for (int ms = 0; ms < 2; ms++) {
        const int r0 = m0 + wm * 32 + ms * 16 + (lane >> 2);
        #pragma unroll
        for (int ns = 0; ns < 8; ns++) {
            const int col = n0 + wn * 64 + ns * 8 + (lane & 3) * 2;
            const float b0 = bias[col], b1 = bias[col + 1];
            float2 v0 = make_float2(acc[ms][ns][0] + b0, acc[ms][ns][1] + b1);
            float2 v1 = make_float2(acc[ms][ns][2] + b0, acc[ms][ns][3] + b1);
            if (mode == 0) {
                *(float2*)(Cout + (size_t)r0 * Ncols + col) = v0;
                *(float2*)(Cout + (size_t)(r0 + 8) * Ncols + col) = v1;
            } else {
                const int which = col >> 10;
                const int d  = col & 1023;
                const int h  = d >> 6;
                const int dd = d & 63;
                __nv_bfloat16 *dh, *dl;
                float sc = 1.0f;
                if (which == 0)      { dh = g_qh; dl = g_ql; sc = LSC; }
                else if (which == 1) { dh = g_kh; dl = g_kl; }
                else                 { dh = g_vh; dl = g_vl; }
                {
                    const int b = r0 >> 11, t = r0 & 2047;
                    const size_t idx =
                        (((size_t)(b * HEADS + h)) * SEQ + t) * HDIM + dd;
                    split_store(dh, dl, idx, v0.x * sc, v0.y * sc);
                }
                {
                    const int r1 = r0 + 8;
                    const int b = r1 >> 11, t = r1 & 2047;
                    const size_t idx =
                        (((size_t)(b * HEADS + h)) * SEQ + t) * HDIM + dd;
                    split_store(dh, dl, idx, v1.x * sc, v1.y * sc);
                }
            }
        }
    }
}

// ---------------------------------------------------------------------------
// Flash attention (causal) on mma.sync, split-bf16 throughout.
// CTA: 128 threads / 4 warps, Q tile 128x64; K/V tiles 64 keys, 2-stage.
// Output written directly as split bf16 to g_a_hi/g_a_lo.
// ---------------------------------------------------------------------------
#define ROWF_B 144                       // 72 bf16 padded row (conflict-free)
#define QH_OFF 0
#define QL_OFF (128 * ROWF_B)            // 18432
#define KV_OFF (2 * 128 * ROWF_B)        // 36864
#define KV_ARR (64 * ROWF_B)             // 9216
#define KV_STG (4 * KV_ARR)              // 36864 (Kh,Kl,Vh,Vl)
#define FLASH_SMEM (KV_OFF + 2 * KV_STG) // 110592

__global__ void __launch_bounds__(128) flash_mma_kernel() {
    extern __shared__ char fsm[];
    const uint32_t base = smem_u32(fsm);
    const int tid = threadIdx.x, lane = tid & 31, wq = tid >> 5;
    const int qt = blockIdx.x, bh = blockIdx.y;
    const size_t hoff = (size_t)bh * SEQ * HDIM;

    const int arow = lane & 15, aseg = lane >> 4;       // Q A-frag
    const int nrow = (lane & 7) + ((lane >> 4) << 3);   // K B-frag
    const int kseg = (lane >> 3) & 1;
    const int vkr = lane & 7, vmi = lane >> 3;          // V trans B-frag

    // issue Q tile (hi+lo): 2 x 128 rows x 8 chunks
    {
        const __nv_bfloat16* qsrc[2] = {g_qh + hoff + (size_t)qt * 128 * HDIM,
                                        g_ql + hoff + (size_t)qt * 128 * HDIM};
        #pragma unroll
        for (int c = 0; c < 16; c++) {
            const int g = tid + c * 128;
            const int arr = g >> 10, t = g & 1023;
            const int row = t >> 3, seg = t & 7;
            CP16(base + (arr ? QL_OFF : QH_OFF) + row * ROWF_B + seg * 16,
                 qsrc[arr] + row * HDIM + seg * 8);
        }
        CP_COMMIT();
    }

    #define ISSUE_KV(jt_, st_) do {                                              \
        const __nv_bfloat16* ksrc_[4] = {g_kh + hoff + (size_t)(jt_) * 64 * HDIM, \
                                         g_kl + hoff + (size_t)(jt_) * 64 * HDIM, \
                                         g_vh + hoff + (size_t)(jt_) * 64 * HDIM, \
                                         g_vl + hoff + (size_t)(jt_) * 64 * HDIM};\
        const uint32_t sb_ = base + KV_OFF + (st_) * KV_STG;                      \
        _Pragma("unroll")                                                         \
        for (int c_ = 0; c_ < 16; c_++) {                                         \
            const int g_ = tid + c_ * 128;                                        \
            const int arr_ = g_ >> 9, t_ = g_ & 511;                              \
            const int row_ = t_ >> 3, seg_ = t_ & 7;                              \
            CP16(sb_ + arr_ * KV_ARR + row_ * ROWF_B + seg_ * 16,                 \
                 ksrc_[arr_] + row_ * HDIM + seg_ * 8);                           \
        }                                                                         \
        CP_COMMIT();                                                              \
    } while (0)

    float oacc[2][8][4];
    float mrun[2][2], lrun[2][2];
    #pragma unroll
    for (int i = 0; i < 2; i++) {
        #pragma unroll
        for (int j = 0; j < 8; j++)
            #pragma unroll
            for (int c = 0; c < 4; c++) oacc[i][j][c] = 0.f;
        mrun[i][0] = mrun[i][1] = -1e30f;
        lrun[i][0] = lrun[i][1] = 0.f;
    }

    const int jmax = 2 * qt + 1;
    ISSUE_KV(0, 0);

    for (int jt = 0; jt <= jmax; jt++) {
        const int st = jt & 1;
        if (jt < jmax) { ISSUE_KV(jt + 1, st ^ 1); CP_WAIT1(); }
        else           { CP_WAIT0(); }
        __syncthreads();
        const uint32_t kb = base + KV_OFF + st * KV_STG;

        // ---- S = Q K^T (split: hi*hi + hi*lo + lo*hi) ----
        float sacc[2][8][4];
        #pragma unroll
        for (int i = 0; i < 2; i++)
            #pragma unroll
            for (int j = 0; j < 8; j++)
                #pragma unroll
                for (int c = 0; c < 4; c++) sacc[i][j][c] = 0.f;

        #pragma unroll
        for (int ks = 0; ks < 4; ks++) {
            const int kk = ks * 16;
            uint32_t QAh[2][4], QAl[2][4];
            #pragma unroll
            for (int ms = 0; ms < 2; ms++) {
                const uint32_t aoff =
                    (uint32_t)((wq * 32 + ms * 16 + arow) * ROWF_B + (kk + aseg * 8) * 2);
                LDM_X4(QAh[ms], base + QH_OFF + aoff);
                LDM_X4(QAl[ms], base + QL_OFF + aoff);
            }
            uint32_t Bh[8][2], Bl[8][2];
            #pragma unroll
            for (int np = 0; np < 4; np++) {
                const uint32_t boff =
                    (uint32_t)((np * 16 + nrow) * ROWF_B + (kk + kseg * 8) * 2);
                uint32_t t0[4], t1[4];
                LDM_X4(t0, kb + 0 * KV_ARR + boff);
                Bh[np * 2][0] = t0[0]; Bh[np * 2][1] = t0[1];
                Bh[np * 2 + 1][0] = t0[2]; Bh[np * 2 + 1][1] = t0[3];
                LDM_X4(t1, kb + 1 * KV_ARR + boff);
                Bl[np * 2][0] = t1[0]; Bl[np * 2][1] = t1[1];
                Bl[np * 2 + 1][0] = t1[2]; Bl[np * 2 + 1][1] = t1[3];
            }
            #pragma unroll
            for (int ms = 0; ms < 2; ms++)
                #pragma unroll
                for (int ns = 0; ns < 8; ns++) {
                    mma16816(sacc[ms][ns], QAh[ms], Bh[ns]);
                    mma16816(sacc[ms][ns], QAh[ms], Bl[ns]);
                    mma16816(sacc[ms][ns], QAl[ms], Bh[ns]);
                }
        }

        // ---- causal mask (only last two k-tiles can intersect diagonal) ----
        if (jt >= 2 * qt) {
            const int rb = qt * 128 + wq * 32 + (lane >> 2);
            #pragma unroll
            for (int ms = 0; ms < 2; ms++) {
                const int r0 = rb + ms * 16, r1 = r0 + 8;
                #pragma unroll
                for (int ns = 0; ns < 8; ns++) {
                    const int col = jt * 64 + ns * 8 + (lane & 3) * 2;
                    if (col     > r0) sacc[ms][ns][0] = -1e30f;
                    if (col + 1 > r0) sacc[ms][ns][1] = -1e30f;
                    if (col     > r1) sacc[ms][ns][2] = -1e30f;
                    if (col + 1 > r1) sacc[ms][ns][3] = -1e30f;
                }
            }
        }

        // ---- online softmax (base-2; scale folded into Q) ----
        #pragma unroll
        for (int ms = 0; ms < 2; ms++)
            #pragma unroll
            for (int hf = 0; hf < 2; hf++) {
                float mx = -1e30f;
                #pragma unroll
                for (int ns = 0; ns < 8; ns++)
                    mx = fmaxf(mx, fmaxf(sacc[ms][ns][2 * hf], sacc[ms][ns][2 * hf + 1]));
                mx = fmaxf(mx, __shfl_xor_sync(0xffffffffu, mx, 1));
                mx = fmaxf(mx, __shfl_xor_sync(0xffffffffu, mx, 2));
                mx = fmaxf(mx, mrun[ms][hf]);
                const float fac = ex2(mrun[ms][hf] - mx);
                mrun[ms][hf] = mx;
                float rs = 0.f;
                #pragma unroll
                for (int ns = 0; ns < 8; ns++) {
                    const float p0 = ex2(sacc[ms][ns][2 * hf] - mx);
                    const float p1 = ex2(sacc[ms][ns][2 * hf + 1] - mx);
                    sacc[ms][ns][2 * hf] = p0;
                    sacc[ms][ns][2 * hf + 1] = p1;
                    rs += p0 + p1;
                    oacc[ms][ns][2 * hf] *= fac;
                    oacc[ms][ns][2 * hf + 1] *= fac;
                }
                rs += __shfl_xor_sync(0xffffffffu, rs, 1);
                rs += __shfl_xor_sync(0xffffffffu, rs, 2);
                lrun[ms][hf] = lrun[ms][hf] * fac + rs;
            }

        // ---- O += P V  (P split hi/lo in regs; V via ldmatrix.trans) ----
        #pragma unroll
        for (int ks = 0; ks < 4; ks++) {
            uint32_t Pah[2][4], Pal[2][4];
            #pragma unroll
            for (int ms = 0; ms < 2; ms++) {
                splitpack(sacc[ms][2 * ks][0],     sacc[ms][2 * ks][1],     Pah[ms][0], Pal[ms][0]);
                splitpack(sacc[ms][2 * ks][2],     sacc[ms][2 * ks][3],     Pah[ms][1], Pal[ms][1]);
                splitpack(sacc[ms][2 * ks + 1][0], sacc[ms][2 * ks + 1][1], Pah[ms][2], Pal[ms][2]);
                splitpack(sacc[ms][2 * ks + 1][2], sacc[ms][2 * ks + 1][3], Pah[ms][3], Pal[ms][3]);
            }
            uint32_t Vbh[8][2], Vbl[8][2];
            #pragma unroll
            for (int ng = 0; ng < 4; ng++) {
                const uint32_t vro =
                    (uint32_t)((ks * 16 + (vmi & 1) * 8 + vkr) * ROWF_B +
                               (ng * 16 + (vmi >> 1) * 8) * 2);
                uint32_t t0[4], t1[4];
                LDM_X4_T(t0, kb + 2 * KV_ARR + vro);
                Vbh[ng * 2][0] = t0[0]; Vbh[ng * 2][1] = t0[1];
                Vbh[ng * 2 + 1][0] = t0[2]; Vbh[ng * 2 + 1][1] = t0[3];
                LDM_X4_T(t1, kb + 3 * KV_ARR + vro);
                Vbl[ng * 2][0] = t1[0]; Vbl[ng * 2][1] = t1[1];
                Vbl[ng * 2 + 1][0] = t1[2]; Vbl[ng * 2 + 1][1] = t1[3];
            }
            #pragma unroll
            for (int ms = 0; ms < 2; ms++)
                #pragma unroll
                for (int og = 0; og < 8; og++) {
                    mma16816(oacc[ms][og], Pah[ms], Vbh[og]);
                    mma16816(oacc[ms][og], Pah[ms], Vbl[og]);
                    mma16816(oacc[ms][og], Pal[ms], Vbh[og]);
                }
        }
        __syncthreads();
    }

    // ---- epilogue: normalize, split-store into g_a_hi/g_a_lo ----
    const int b = bh >> 4, hh = bh & 15;
    #pragma unroll
    for (int ms = 0; ms < 2; ms++)
        #pragma unroll
        for (int hf = 0; hf < 2; hf++) {
            const float inv = 1.f / lrun[ms][hf];
            const int r = qt * 128 + wq * 32 + ms * 16 + (lane >> 2) + hf * 8;
            const size_t grow = ((size_t)b * SEQ + r) * DIM;
            #pragma unroll
            for (int ns = 0; ns < 8; ns++) {
                const int col = hh * 64 + ns * 8 + (lane & 3) * 2;
                split_store(g_a_hi, g_a_lo, grow + col,
                            oacc[ms][ns][2 * hf] * inv,
                            oacc[ms][ns][2 * hf + 1] * inv);
            }
        }
}

// ---------------------------------------------------------------------------
// Launch
// ---------------------------------------------------------------------------
extern "C" void kernel_launch(void* const* d_in, const int* in_sizes, int n_in,
                              void* d_out, int out_size) {
    const float* x      = (const float*)d_in[0];
    const float* W_attn = (const float*)d_in[1];
    const float* b_attn = (const float*)d_in[2];
    const float* W_proj = (const float*)d_in[3];
    const float* b_proj = (const float*)d_in[4];
    float* out = (float*)d_out;
    (void)in_sizes; (void)n_in; (void)out_size;

    cudaFuncSetAttribute(mma_gemm_kernel,
                         cudaFuncAttributeMaxDynamicSharedMemorySize, DYN_SMEM);
    cudaFuncSetAttribute(flash_mma_kernel,
                         cudaFuncAttributeMaxDynamicSharedMemorySize, FLASH_SMEM);

    wsplit_kernel<<<dim3(3072 / 32, 1024 / 32), dim3(32, 8)>>>(W_attn, 3072, 1);
    wsplit_kernel<<<dim3(1024 / 32, 1024 / 32), dim3(32, 8)>>>(W_proj, 1024, 0);
    asplit_kernel<<<8192, 256>>>(x);

    // QKV GEMM -> split-bf16 q/k/v
    mma_gemm_kernel<<<dim3(3072 / 128, 8192 / 128), 256, DYN_SMEM>>>(
        b_attn, nullptr, 3072, /*mode=*/1);

    // causal flash attention on tensor cores -> g_a_hi/g_a_lo
    flash_mma_kernel<<<dim3(SEQ / 128, BATCH * HEADS), 128, FLASH_SMEM>>>();

    // output projection
    mma_gemm_kernel<<<dim3(1024 / 128, 8192 / 128), 256, DYN_SMEM>>>(
        b_proj, out, 1024, /*mode=*/0);
}

// round 15
// speedup vs baseline: 3.5301x; 1.1240x over previous
#include <cuda_runtime.h>
#include <cuda_bf16.h>
#include <cstdint>
#include <cstddef>

// Problem shape: B=4, T=2048, D=1024, H=16, hd=64
#define BATCH 4
#define SEQ   2048
#define DIM   1024
#define HEADS 16
#define HDIM  64

// ---------------------------------------------------------------------------
// Device-global scratch (no dynamic allocation allowed)
// q/k/v stored as split bf16 hi/lo, [b*H+h][t][hd]; Q pre-scaled by log2e/8.
// ---------------------------------------------------------------------------
__device__ __align__(16) __nv_bfloat16 g_qh[BATCH * HEADS * SEQ * HDIM];
__device__ __align__(16) __nv_bfloat16 g_ql[BATCH * HEADS * SEQ * HDIM];
__device__ __align__(16) __nv_bfloat16 g_kh[BATCH * HEADS * SEQ * HDIM];
__device__ __align__(16) __nv_bfloat16 g_kl[BATCH * HEADS * SEQ * HDIM];
__device__ __align__(16) __nv_bfloat16 g_vh[BATCH * HEADS * SEQ * HDIM];
__device__ __align__(16) __nv_bfloat16 g_vl[BATCH * HEADS * SEQ * HDIM];

// split-bf16 GEMM operands: weights transposed [N][K]; activations [M][K]
__device__ __align__(16) __nv_bfloat16 g_wat_hi[3072 * 1024];
__device__ __align__(16) __nv_bfloat16 g_wat_lo[3072 * 1024];
__device__ __align__(16) __nv_bfloat16 g_wpt_hi[1024 * 1024];
__device__ __align__(16) __nv_bfloat16 g_wpt_lo[1024 * 1024];
__device__ __align__(16) __nv_bfloat16 g_a_hi[8192 * 1024];
__device__ __align__(16) __nv_bfloat16 g_a_lo[8192 * 1024];

// log2(e) / sqrt(hd)
#define LSC 0.18033688011112042f

// ---------------------------------------------------------------------------
// Portable PTX helpers (sm_80 feature set only; tcgen05/TMA rejected by
// the harness's compute_103 virtual-arch build)
// ---------------------------------------------------------------------------
__device__ __forceinline__ uint32_t smem_u32(const void* p) {
    uint32_t a;
    asm("{ .reg .u64 t; cvta.to.shared.u64 t, %1; cvt.u32.u64 %0, t; }"
        : "=r"(a) : "l"(p));
    return a;
}

#define CP16(smem, gptr) \
    asm volatile("cp.async.cg.shared.global [%0], [%1], 16;" \
                 :: "r"(smem), "l"(gptr))
#define CP_COMMIT() asm volatile("cp.async.commit_group;" ::: "memory")
#define CP_WAIT1()  asm volatile("cp.async.wait_group 1;" ::: "memory")
#define CP_WAIT0()  asm volatile("cp.async.wait_group 0;" ::: "memory")

#define LDM_X4(r, addr) \
    asm volatile("ldmatrix.sync.aligned.m8n8.x4.shared.b16 {%0,%1,%2,%3}, [%4];" \
                 : "=r"((r)[0]), "=r"((r)[1]), "=r"((r)[2]), "=r"((r)[3]) \
                 : "r"(addr))

#define LDM_X4_T(r, addr) \
    asm volatile("ldmatrix.sync.aligned.m8n8.x4.trans.shared.b16 {%0,%1,%2,%3}, [%4];" \
                 : "=r"((r)[0]), "=r"((r)[1]), "=r"((r)[2]), "=r"((r)[3]) \
                 : "r"(addr))

__device__ __forceinline__ void mma16816(float* d, const uint32_t* a,
                                         const uint32_t* b) {
    asm volatile(
        "mma.sync.aligned.m16n8k16.row.col.f32.bf16.bf16.f32 "
        "{%0,%1,%2,%3}, {%4,%5,%6,%7}, {%8,%9}, {%0,%1,%2,%3};"
        : "+f"(d[0]), "+f"(d[1]), "+f"(d[2]), "+f"(d[3])
        : "r"(a[0]), "r"(a[1]), "r"(a[2]), "r"(a[3]), "r"(b[0]), "r"(b[1]));
}

__device__ __forceinline__ float ex2(float x) {
    float r;
    asm("ex2.approx.f32 %0, %1;" : "=f"(r) : "f"(x));
    return r;
}

// split (a,b) into bf16 hi/lo packed pairs (low half = a)
__device__ __forceinline__ void splitpack(float a, float b,
                                          uint32_t& hi, uint32_t& lo) {
    __nv_bfloat16 ha = __float2bfloat16(a), hb = __float2bfloat16(b);
    float la = a - __bfloat162float(ha), lb = b - __bfloat162float(hb);
    __nv_bfloat162 hv; hv.x = ha; hv.y = hb;
    __nv_bfloat162 lv; lv.x = __float2bfloat16(la); lv.y = __float2bfloat16(lb);
    hi = *reinterpret_cast<uint32_t*>(&hv);
    lo = *reinterpret_cast<uint32_t*>(&lv);
}

__device__ __forceinline__ void split_store(__nv_bfloat16* dh, __nv_bfloat16* dl,
                                            size_t idx, float a, float b) {
    __nv_bfloat16 ha = __float2bfloat16(a), hb = __float2bfloat16(b);
    float la = a - __bfloat162float(ha), lb = b - __bfloat162float(hb);
    __nv_bfloat162 hv; hv.x = ha; hv.y = hb;
    __nv_bfloat162 lv; lv.x = __float2bfloat16(la); lv.y = __float2bfloat16(lb);
    *reinterpret_cast<__nv_bfloat162*>(dh + idx) = hv;
    *reinterpret_cast<__nv_bfloat162*>(dl + idx) = lv;
}

// ---------------------------------------------------------------------------
// Weight transpose + split: W[K=1024][N] -> Wt_hi/lo[N][1024] bf16
// ---------------------------------------------------------------------------
__global__ void __launch_bounds__(256) wsplit_kernel(const float* __restrict__ W,
                                                     int N, int which) {
    __shared__ float tile[32][33];
    __nv_bfloat16* hi = which ? g_wat_hi : g_wpt_hi;
    __nv_bfloat16* lo = which ? g_wat_lo : g_wpt_lo;
    const int n0 = blockIdx.x * 32, k0 = blockIdx.y * 32;
    const int tx = threadIdx.x, ty = threadIdx.y;
    for (int i = ty; i < 32; i += 8)
        tile[i][tx] = W[(size_t)(k0 + i) * N + n0 + tx];
    __syncthreads();
    for (int j = ty; j < 32; j += 8) {
        const int n = n0 + j, k = k0 + tx;
        const float v = tile[tx][j];
        const __nv_bfloat16 h = __float2bfloat16(v);
        hi[(size_t)n * 1024 + k] = h;
        lo[(size_t)n * 1024 + k] = __float2bfloat16(v - __bfloat162float(h));
    }
}

// ---------------------------------------------------------------------------
// Activation split: x[M][1024] fp32 -> g_a_hi/lo bf16
// ---------------------------------------------------------------------------
__global__ void __launch_bounds__(256) asplit_kernel(const float* __restrict__ src) {
    const int i = blockIdx.x * 256 + threadIdx.x;
    const float4 v = ((const float4*)src)[i];
    __nv_bfloat16 h0 = __float2bfloat16(v.x), h1 = __float2bfloat16(v.y);
    __nv_bfloat16 h2 = __float2bfloat16(v.z), h3 = __float2bfloat16(v.w);
    __nv_bfloat16 l0 = __float2bfloat16(v.x - __bfloat162float(h0));
    __nv_bfloat16 l1 = __float2bfloat16(v.y - __bfloat162float(h1));
    __nv_bfloat16 l2 = __float2bfloat16(v.z - __bfloat162float(h2));
    __nv_bfloat16 l3 = __float2bfloat16(v.w - __bfloat162float(h3));
    uint2 ph, pl;
    ph.x = (uint32_t)reinterpret_cast<unsigned short&>(h0) |
           ((uint32_t)reinterpret_cast<unsigned short&>(h1) << 16);
    ph.y = (uint32_t)reinterpret_cast<unsigned short&>(h2) |
           ((uint32_t)reinterpret_cast<unsigned short&>(h3) << 16);
    pl.x = (uint32_t)reinterpret_cast<unsigned short&>(l0) |
           ((uint32_t)reinterpret_cast<unsigned short&>(l1) << 16);
    pl.y = (uint32_t)reinterpret_cast<unsigned short&>(l2) |
           ((uint32_t)reinterpret_cast<unsigned short&>(l3) << 16);
    ((uint2*)g_a_hi)[i] = ph;
    ((uint2*)g_a_lo)[i] = pl;
}

// ---------------------------------------------------------------------------
// mma.sync split-bf16 GEMM. Pending change: B-fragment live range shrunk
// (load one ldmatrix pair, consume immediately) + __launch_bounds__(256,2)
// to force <=128 regs so 2 CTAs/SM become resident.
// ---------------------------------------------------------------------------
#define KT     32
#define ROWB   80
#define TILE_B (128 * ROWB)
#define STAGE  (4 * TILE_B)
#define DYN_SMEM (2 * STAGE)

__global__ void __launch_bounds__(256, 2) mma_gemm_kernel(const float* __restrict__ bias,
                                                          float* __restrict__ Cout,
                                                          int Ncols, int mode) {
    extern __shared__ char sm[];
    const int tid = threadIdx.x, lane = tid & 31, wid = tid >> 5;
    const int wm = wid & 3, wn = wid >> 2;
    const int n0 = blockIdx.x * 128, m0 = blockIdx.y * 128;
    const uint32_t base = smem_u32(sm);

    const __nv_bfloat16* srcs[4] = {
        g_a_hi + (size_t)m0 * 1024,
        g_a_lo + (size_t)m0 * 1024,
        (mode ? g_wat_hi : g_wpt_hi) + (size_t)n0 * 1024,
        (mode ? g_wat_lo : g_wpt_lo) + (size_t)n0 * 1024};

    float acc[2][8][4];
    #pragma unroll
    for (int i = 0; i < 2; i++)
        #pragma unroll
        for (int j = 0; j < 8; j++)
            #pragma unroll
            for (int c = 0; c < 4; c++) acc[i][j][c] = 0.f;

    const int arow = lane & 15, aseg = lane >> 4;
    const int nrow = (lane & 7) + ((lane >> 4) << 3);
    const int kseg = (lane >> 3) & 1;

    #define ISSUE_STAGE(s) do {                                                   \
        const int _buf = (s) & 1;                                                 \
        const int _k0 = (s) * KT;                                                 \
        const uint32_t _sb = base + _buf * STAGE;                                 \
        _Pragma("unroll")                                                         \
        for (int _c = 0; _c < 8; _c++) {                                          \
            const int _g = tid + _c * 256;                                        \
            const int _tile = _g >> 9, _t = _g & 511;                             \
            const int _row = _t >> 2, _seg = _t & 3;                              \
            CP16(_sb + _tile * TILE_B + _row * ROWB + _seg * 16,                  \
                 srcs[_tile] + (size_t)_row * 1024 + _k0 + _seg * 8);             \
        }                                                                         \
        CP_COMMIT();                                                              \
    } while (0)

    ISSUE_STAGE(0);
    for (int s = 0; s < 32; s++) {
        if (s + 1 < 32) { ISSUE_STAGE(s + 1); CP_WAIT1(); }
        else            { CP_WAIT0(); }
        __syncthreads();

        const uint32_t sb  = base + (s & 1) * STAGE;
        const uint32_t sAh = sb, sAl = sb + TILE_B;
        const uint32_t sBh = sb + 2 * TILE_B, sBl = sb + 3 * TILE_B;

        #pragma unroll
        for (int ks = 0; ks < 2; ks++) {
            const int kk = ks * 16;
            uint32_t Ah[2][4], Al[2][4];
            #pragma unroll
            for (int ms = 0; ms < 2; ms++) {
                const uint32_t aoff =
                    (uint32_t)((wm * 32 + ms * 16 + arow) * ROWB + (kk + aseg * 8) * 2);
                LDM_X4(Ah[ms], sAh + aoff);
                LDM_X4(Al[ms], sAl + aoff);
            }
            // B loaded in 2-slice chunks and consumed immediately (low reg pressure)
            #pragma unroll
            for (int np = 0; np < 4; np++) {
                const uint32_t boff =
                    (uint32_t)((wn * 64 + np * 16 + nrow) * ROWB + (kk + kseg * 8) * 2);
                uint32_t t0[4], t1[4];
                LDM_X4(t0, sBh + boff);
                LDM_X4(t1, sBl + boff);
                #pragma unroll
                for (int ms = 0; ms < 2; ms++) {
                    mma16816(acc[ms][2 * np],     Ah[ms], &t0[0]);
                    mma16816(acc[ms][2 * np],     Ah[ms], &t1[0]);
                    mma16816(acc[ms][2 * np],     Al[ms], &t0[0]);
                    mma16816(acc[ms][2 * np + 1], Ah[ms], &t0[2]);
                    mma16816(acc[ms][2 * np + 1], Ah[ms], &t1[2]);
                    mma16816(acc[ms][2 * np + 1], Al[ms], &t0[2]);
                }
            }
        }
        __syncthreads();
    }

    #pragma unroll
    for (int ms = 0; ms < 2; ms++) {
        const int r0 = m0 + wm * 32 + ms * 16 + (lane >> 2);
        #pragma unroll
        for (int ns = 0; ns < 8; ns++) {
            const int col = n0 + wn * 64 + ns * 8 + (lane & 3) * 2;
            const float b0 = bias[col], b1 = bias[col + 1];
            float2 v0 = make_float2(acc[ms][ns][0] + b0, acc[ms][ns][1] + b1);
            float2 v1 = make_float2(acc[ms][ns][2] + b0, acc[ms][ns][3] + b1);
            if (mode == 0) {
                *(float2*)(Cout + (size_t)r0 * Ncols + col) = v0;
                *(float2*)(Cout + (size_t)(r0 + 8) * Ncols + col) = v1;
            } else {
                const int which = col >> 10;
                const int d  = col & 1023;
                const int h  = d >> 6;
                const int dd = d & 63;
                __nv_bfloat16 *dh, *dl;
                float sc = 1.0f;
                if (which == 0)      { dh = g_qh; dl = g_ql; sc = LSC; }
                else if (which == 1) { dh = g_kh; dl = g_kl; }
                else                 { dh = g_vh; dl = g_vl; }
                {
                    const int b = r0 >> 11, t = r0 & 2047;
                    const size_t idx =
                        (((size_t)(b * HEADS + h)) * SEQ + t) * HDIM + dd;
                    split_store(dh, dl, idx, v0.x * sc, v0.y * sc);
                }
                {
                    const int r1 = r0 + 8;
                    const int b = r1 >> 11, t = r1 & 2047;
                    const size_t idx =
                        (((size_t)(b * HEADS + h)) * SEQ + t) * HDIM + dd;
                    split_store(dh, dl, idx, v1.x * sc, v1.y * sc);
                }
            }
        }
    }
}

// ---------------------------------------------------------------------------
// Flash attention (causal) on mma.sync — unchanged from the R12 WIN.
// ---------------------------------------------------------------------------
#define ROWF_B 144
#define QH_OFF 0
#define QL_OFF (128 * ROWF_B)
#define KV_OFF (2 * 128 * ROWF_B)
#define KV_ARR (64 * ROWF_B)
#define KV_STG (4 * KV_ARR)
#define FLASH_SMEM (KV_OFF + 2 * KV_STG)

__global__ void __launch_bounds__(128) flash_mma_kernel() {
    extern __shared__ char fsm[];
    const uint32_t base = smem_u32(fsm);
    const int tid = threadIdx.x, lane = tid & 31, wq = tid >> 5;
    const int qt = blockIdx.x, bh = blockIdx.y;
    const size_t hoff = (size_t)bh * SEQ * HDIM;

    const int arow = lane & 15, aseg = lane >> 4;
    const int nrow = (lane & 7) + ((lane >> 4) << 3);
    const int kseg = (lane >> 3) & 1;
    const int vkr = lane & 7, vmi = lane >> 3;

    {
        const __nv_bfloat16* qsrc[2] = {g_qh + hoff + (size_t)qt * 128 * HDIM,
                                        g_ql + hoff + (size_t)qt * 128 * HDIM};
        #pragma unroll
        for (int c = 0; c < 16; c++) {
            const int g = tid + c * 128;
            const int arr = g >> 10, t = g & 1023;
            const int row = t >> 3, seg = t & 7;
            CP16(base + (arr ? QL_OFF : QH_OFF) + row * ROWF_B + seg * 16,
                 qsrc[arr] + row * HDIM + seg * 8);
        }
        CP_COMMIT();
    }

    #define ISSUE_KV(jt_, st_) do {                                              \
        const __nv_bfloat16* ksrc_[4] = {g_kh + hoff + (size_t)(jt_) * 64 * HDIM, \
                                         g_kl + hoff + (size_t)(jt_) * 64 * HDIM, \
                                         g_vh + hoff + (size_t)(jt_) * 64 * HDIM, \
                                         g_vl + hoff + (size_t)(jt_) * 64 * HDIM};\
        const uint32_t sb_ = base + KV_OFF + (st_) * KV_STG;                      \
        _Pragma("unroll")                                                         \
        for (int c_ = 0; c_ < 16; c_++) {                                         \
            const int g_ = tid + c_ * 128;                                        \
            const int arr_ = g_ >> 9, t_ = g_ & 511;                              \
            const int row_ = t_ >> 3, seg_ = t_ & 7;                              \
            CP16(sb_ + arr_ * KV_ARR + row_ * ROWF_B + seg_ * 16,                 \
                 ksrc_[arr_] + row_ * HDIM + seg_ * 8);                           \
        }                                                                         \
        CP_COMMIT();                                                              \
    } while (0)

    float oacc[2][8][4];
    float mrun[2][2], lrun[2][2];
    #pragma unroll
    for (int i = 0; i < 2; i++) {
        #pragma unroll
        for (int j = 0; j < 8; j++)
            #pragma unroll
            for (int c = 0; c < 4; c++) oacc[i][j][c] = 0.f;
        mrun[i][0] = mrun[i][1] = -1e30f;
        lrun[i][0] = lrun[i][1] = 0.f;
    }

    const int jmax = 2 * qt + 1;
    ISSUE_KV(0, 0);

    for (int jt = 0; jt <= jmax; jt++) {
        const int st = jt & 1;
        if (jt < jmax) { ISSUE_KV(jt + 1, st ^ 1); CP_WAIT1(); }
        else           { CP_WAIT0(); }
        __syncthreads();
        const uint32_t kb = base + KV_OFF + st * KV_STG;

        float sacc[2][8][4];
        #pragma unroll
        for (int i = 0; i < 2; i++)
            #pragma unroll
            for (int j = 0; j < 8; j++)
                #pragma unroll
                for (int c = 0; c < 4; c++) sacc[i][j][c] = 0.f;

        #pragma unroll
        for (int ks = 0; ks < 4; ks++) {
            const int kk = ks * 16;
            uint32_t QAh[2][4], QAl[2][4];
            #pragma unroll
            for (int ms = 0; ms < 2; ms++) {
                const uint32_t aoff =
                    (uint32_t)((wq * 32 + ms * 16 + arow) * ROWF_B + (kk + aseg * 8) * 2);
                LDM_X4(QAh[ms], base + QH_OFF + aoff);
                LDM_X4(QAl[ms], base + QL_OFF + aoff);
            }
            #pragma unroll
            for (int np = 0; np < 4; np++) {
                const uint32_t boff =
                    (uint32_t)((np * 16 + nrow) * ROWF_B + (kk + kseg * 8) * 2);
                uint32_t t0[4], t1[4];
                LDM_X4(t0, kb + 0 * KV_ARR + boff);
                LDM_X4(t1, kb + 1 * KV_ARR + boff);
                #pragma unroll
                for (int ms = 0; ms < 2; ms++) {
                    mma16816(sacc[ms][2 * np],     QAh[ms], &t0[0]);
                    mma16816(sacc[ms][2 * np],     QAh[ms], &t1[0]);
                    mma16816(sacc[ms][2 * np],     QAl[ms], &t0[0]);
                    mma16816(sacc[ms][2 * np + 1], QAh[ms], &t0[2]);
                    mma16816(sacc[ms][2 * np + 1], QAh[ms], &t1[2]);
                    mma16816(sacc[ms][2 * np + 1], QAl[ms], &t0[2]);
                }
            }
        }

        if (jt >= 2 * qt) {
            const int rb = qt * 128 + wq * 32 + (lane >> 2);
            #pragma unroll
            for (int ms = 0; ms < 2; ms++) {
                const int r0 = rb + ms * 16, r1 = r0 + 8;
                #pragma unroll
                for (int ns = 0; ns < 8; ns++) {
                    const int col = jt * 64 + ns * 8 + (lane & 3) * 2;
                    if (col     > r0) sacc[ms][ns][0] = -1e30f;
                    if (col + 1 > r0) sacc[ms][ns][1] = -1e30f;
                    if (col     > r1) sacc[ms][ns][2] = -1e30f;
                    if (col + 1 > r1) sacc[ms][ns][3] = -1e30f;
                }
            }
        }

        #pragma unroll
        for (int ms = 0; ms < 2; ms++)
            #pragma unroll
            for (int hf = 0; hf < 2; hf++) {
                float mx = -1e30f;
                #pragma unroll
                for (int ns = 0; ns < 8; ns++)
                    mx = fmaxf(mx, fmaxf(sacc[ms][ns][2 * hf], sacc[ms][ns][2 * hf + 1]));
                mx = fmaxf(mx, __shfl_xor_sync(0xffffffffu, mx, 1));
                mx = fmaxf(mx, __shfl_xor_sync(0xffffffffu, mx, 2));
                mx = fmaxf(mx, mrun[ms][hf]);
                const float fac = ex2(mrun[ms][hf] - mx);
                mrun[ms][hf] = mx;
                float rs = 0.f;
                #pragma unroll
                for (int ns = 0; ns < 8; ns++) {
                    const float p0 = ex2(sacc[ms][ns][2 * hf] - mx);
                    const float p1 = ex2(sacc[ms][ns][2 * hf + 1] - mx);
                    sacc[ms][ns][2 * hf] = p0;
                    sacc[ms][ns][2 * hf + 1] = p1;
                    rs += p0 + p1;
                    oacc[ms][ns][2 * hf] *= fac;
                    oacc[ms][ns][2 * hf + 1] *= fac;
                }
                rs += __shfl_xor_sync(0xffffffffu, rs, 1);
                rs += __shfl_xor_sync(0xffffffffu, rs, 2);
                lrun[ms][hf] = lrun[ms][hf] * fac + rs;
            }

        #pragma unroll
        for (int ks = 0; ks < 4; ks++) {
            uint32_t Pah[2][4], Pal[2][4];
            #pragma unroll
            for (int ms = 0; ms < 2; ms++) {
                splitpack(sacc[ms][2 * ks][0],     sacc[ms][2 * ks][1],     Pah[ms][0], Pal[ms][0]);
                splitpack(sacc[ms][2 * ks][2],     sacc[ms][2 * ks][3],     Pah[ms][1], Pal[ms][1]);
                splitpack(sacc[ms][2 * ks + 1][0], sacc[ms][2 * ks + 1][1], Pah[ms][2], Pal[ms][2]);
                splitpack(sacc[ms][2 * ks + 1][2], sacc[ms][2 * ks + 1][3], Pah[ms][3], Pal[ms][3]);
            }
            #pragma unroll
            for (int ng = 0; ng < 4; ng++) {
                const uint32_t vro =
                    (uint32_t)((ks * 16 + (vmi & 1) * 8 + vkr) * ROWF_B +
                               (ng * 16 + (vmi >> 1) * 8) * 2);
                uint32_t t0[4], t1[4];
                LDM_X4_T(t0, kb + 2 * KV_ARR + vro);
                LDM_X4_T(t1, kb + 3 * KV_ARR + vro);
                #pragma unroll
                for (int ms = 0; ms < 2; ms++) {
                    mma16816(oacc[ms][2 * ng],     Pah[ms], &t0[0]);
                    mma16816(oacc[ms][2 * ng],     Pah[ms], &t1[0]);
                    mma16816(oacc[ms][2 * ng],     Pal[ms], &t0[0]);
                    mma16816(oacc[ms][2 * ng + 1], Pah[ms], &t0[2]);
                    mma16816(oacc[ms][2 * ng + 1], Pah[ms], &t1[2]);
                    mma16816(oacc[ms][2 * ng + 1], Pal[ms], &t0[2]);
                }
            }
        }
        __syncthreads();
    }

    const int b = bh >> 4, hh = bh & 15;
    #pragma unroll
    for (int ms = 0; ms < 2; ms++)
        #pragma unroll
        for (int hf = 0; hf < 2; hf++) {
            const float inv = 1.f / lrun[ms][hf];
            const int r = qt * 128 + wq * 32 + ms * 16 + (lane >> 2) + hf * 8;
            const size_t grow = ((size_t)b * SEQ + r) * DIM;
            #pragma unroll
            for (int ns = 0; ns < 8; ns++) {
                const int col = hh * 64 + ns * 8 + (lane & 3) * 2;
                split_store(g_a_hi, g_a_lo, grow + col,
                            oacc[ms][ns][2 * hf] * inv,
                            oacc[ms][ns][2 * hf + 1] * inv);
            }
        }
}

// ---------------------------------------------------------------------------
// Launch
// ---------------------------------------------------------------------------
extern "C" void kernel_launch(void* const* d_in, const int* in_sizes, int n_in,
                              void* d_out, int out_size) {
    const float* x      = (const float*)d_in[0];
    const float* W_attn = (const float*)d_in[1];
    const float* b_attn = (const float*)d_in[2];
    const float* W_proj = (const float*)d_in[3];
    const float* b_proj = (const float*)d_in[4];
    float* out = (float*)d_out;
    (void)in_sizes; (void)n_in; (void)out_size;

    cudaFuncSetAttribute(mma_gemm_kernel,
                         cudaFuncAttributeMaxDynamicSharedMemorySize, DYN_SMEM);
    cudaFuncSetAttribute(flash_mma_kernel,
                         cudaFuncAttributeMaxDynamicSharedMemorySize, FLASH_SMEM);

    wsplit_kernel<<<dim3(3072 / 32, 1024 / 32), dim3(32, 8)>>>(W_attn, 3072, 1);
    wsplit_kernel<<<dim3(1024 / 32, 1024 / 32), dim3(32, 8)>>>(W_proj, 1024, 0);
    asplit_kernel<<<8192, 256>>>(x);

    // QKV GEMM -> split-bf16 q/k/v
    mma_gemm_kernel<<<dim3(3072 / 128, 8192 / 128), 256, DYN_SMEM>>>(
        b_attn, nullptr, 3072, /*mode=*/1);

    // causal flash attention on tensor cores -> g_a_hi/g_a_lo
    flash_mma_kernel<<<dim3(SEQ / 128, BATCH * HEADS), 128, FLASH_SMEM>>>();

    // output projection
    mma_gemm_kernel<<<dim3(1024 / 128, 8192 / 128), 256, DYN_SMEM>>>(
        b_proj, out, 1024, /*mode=*/0);
}